// round 9
// baseline (speedup 1.0000x reference)
#include <cuda_runtime.h>

#define HH 32
#define WW 32
#define BB 16
#define NPOS 512
#define PIX 8              // pixels per tile (contiguous in one row)
#define THREADS 512
#define GRID 256           // 128 tiles x 2 batch-halves
#define SEGROW 36          // floats per A-segment (32 data + 4 pad)
#define SROW (16 * SEGROW + 4)   // 580 floats per pixel row
#define LHW (NPOS * HH * WW)
#define VROW 12            // halo smem: cols per row (10 used)
#define VBAT 36            // halo smem: floats per batch (3*12)
#define NBAT 8             // batches per block

// Ping-pong state scratch (no device allocation allowed).
__device__ float g_state[2][BB * HH * WW];

__device__ __forceinline__ float sigmoidf(float x) {
    return __fdividef(1.0f, 1.0f + __expf(-x));
}

// 8 products for one bit-triple (va = MSB).
__device__ __forceinline__ void triple8(float va, float vb, float vc, float* P) {
    float ca = 1.0f - va, cb = 1.0f - vb, cc = 1.0f - vc;
    float t0 = cb * cc, t1 = cb * vc, t2 = vb * cc, t3 = vb * vc;
    P[0] = ca * t0; P[1] = ca * t1; P[2] = ca * t2; P[3] = ca * t3;
    P[4] = va * t0; P[5] = va * t1; P[6] = va * t2; P[7] = va * t3;
}

__global__ __launch_bounds__(THREADS, 2)
void asic_layer(const float* __restrict__ src,   // (B,H,W) previous state
                const float* __restrict__ tg,    // (NPOS,H,W) this layer's gates
                float* __restrict__ dst)         // (B,H,W)
{
    __shared__ __align__(16) float s_s[PIX * SROW];      // sigmoid(gates) for 8 pixels
    __shared__ __align__(16) float s_v[NBAT * VBAT];     // state halo for 8 batches

    const int tid = threadIdx.x;
    const int tile  = blockIdx.x >> 1;       // 0..127
    const int bhalf = blockIdx.x & 1;        // batches bhalf*8 .. +7
    const int pixBase = tile * PIX;
    const int hB = pixBase >> 5;             // tile row
    const int w0 = pixBase & 31;             // tile first col
    const int batBase = bhalf * NBAT;

    // ---- issue gate LDG.128s (two combo-halfrows per thread) ----
    const int p0  = tid >> 1;                // combo for chunk 0
    const int ih0 = (tid & 1) * 4;
    float4 g0 = *(const float4*)(tg + p0 * (HH * WW) + pixBase + ih0);
    const int c1  = tid + THREADS;
    const int p1  = c1 >> 1;
    const int ih1 = (c1 & 1) * 4;
    float4 g1 = *(const float4*)(tg + p1 * (HH * WW) + pixBase + ih1);

    // ---- issue halo LDG (240 distinct values: 8 batches x 3 rows x 10 cols) ----
    float wv = 0.0f;
    int vIdx = 0;
    if (tid < NBAT * 30) {
        int b   = tid / 30;
        int rem = tid % 30;
        int r   = rem / 10;
        int c   = rem % 10;
        int row = (hB + r) & 31;
        int col = (w0 - 1 + c) & 31;
        wv = __ldg(src + (batBase + b) * (HH * WW) + row * WW + col);
        vIdx = b * VBAT + r * VROW + c;
    }

    // ---- sigmoid + stage gates (MUFU work overlaps LDG latency) ----
    {
        int base = (p0 >> 5) * SEGROW + (p0 & 31);
        s_s[(ih0 + 0) * SROW + base] = sigmoidf(g0.x);
        s_s[(ih0 + 1) * SROW + base] = sigmoidf(g0.y);
        s_s[(ih0 + 2) * SROW + base] = sigmoidf(g0.z);
        s_s[(ih0 + 3) * SROW + base] = sigmoidf(g0.w);
        base = (p1 >> 5) * SEGROW + (p1 & 31);
        s_s[(ih1 + 0) * SROW + base] = sigmoidf(g1.x);
        s_s[(ih1 + 1) * SROW + base] = sigmoidf(g1.y);
        s_s[(ih1 + 2) * SROW + base] = sigmoidf(g1.z);
        s_s[(ih1 + 3) * SROW + base] = sigmoidf(g1.w);
    }
    if (tid < NBAT * 30) s_v[vIdx] = wv;
    __syncthreads();

    // ---- thread mapping: seg(16) x batch-pair(4) x pixel(8) ----
    const int seg  = tid & 15;           // A = top 4 bits of combo j
    const int bp   = (tid >> 4) & 3;     // local batches bp and bp+4
    const int pixL = tid >> 6;           // 0..7
    const int pixel = pixBase + pixL;
    const int lb0 = bp, lb1 = bp + 4;

    // ---- read both batches' 3x3 windows from smem (broadcast) ----
    float v0[9], v1[9];
#pragma unroll
    for (int i0 = 0; i0 < 3; i0++) {
#pragma unroll
        for (int i1 = 0; i1 < 3; i1++) {
            int c = i0 * VROW + pixL + i1;
            v0[i0 * 3 + i1] = s_v[lb0 * VBAT + c];
            v1[i0 * 3 + i1] = s_v[lb1 * VBAT + c];
        }
    }

    // ---- partial products ----
    // A = j>>5 (m0..m3, fixed = seg), B = (j>>2)&7 (m4..m6), C = j&3 (m7,m8)
    float PB0[8], PB1[8];
    triple8(v0[4], v0[5], v0[6], PB0);
    triple8(v1[4], v1[5], v1[6], PB1);

    float PC0[4], PC1[4];
    {
        float c7 = 1.0f - v0[7], c8 = 1.0f - v0[8];
        PC0[0] = c7 * c8; PC0[1] = c7 * v0[8]; PC0[2] = v0[7] * c8; PC0[3] = v0[7] * v0[8];
        float d7 = 1.0f - v1[7], d8 = 1.0f - v1[8];
        PC1[0] = d7 * d8; PC1[1] = d7 * v1[8]; PC1[2] = v1[7] * d8; PC1[3] = v1[7] * v1[8];
    }

    const float PA0 = (((seg & 8) ? v0[0] : 1.0f - v0[0]) * ((seg & 4) ? v0[1] : 1.0f - v0[1]))
                    * (((seg & 2) ? v0[2] : 1.0f - v0[2]) * ((seg & 1) ? v0[3] : 1.0f - v0[3]));
    const float PA1 = (((seg & 8) ? v1[0] : 1.0f - v1[0]) * ((seg & 4) ? v1[1] : 1.0f - v1[1]))
                    * (((seg & 2) ? v1[2] : 1.0f - v1[2]) * ((seg & 1) ? v1[3] : 1.0f - v1[3]));

    // ---- contraction: 32 combos, fma chains, each gate read feeds 2 batches ----
    const float* sp = s_s + pixL * SROW + seg * SEGROW;
    float a0e = 0.0f, a0o = 0.0f, a1e = 0.0f, a1o = 0.0f;
#pragma unroll
    for (int b = 0; b < 8; b += 2) {
        float4 r0 = *(const float4*)(sp + b * 4);
        float4 r1 = *(const float4*)(sp + b * 4 + 4);

        float i00 = PC0[0] * r0.x;
        i00 = fmaf(PC0[1], r0.y, i00);
        i00 = fmaf(PC0[2], r0.z, i00);
        i00 = fmaf(PC0[3], r0.w, i00);
        float i10 = PC1[0] * r0.x;
        i10 = fmaf(PC1[1], r0.y, i10);
        i10 = fmaf(PC1[2], r0.z, i10);
        i10 = fmaf(PC1[3], r0.w, i10);
        float i01 = PC0[0] * r1.x;
        i01 = fmaf(PC0[1], r1.y, i01);
        i01 = fmaf(PC0[2], r1.z, i01);
        i01 = fmaf(PC0[3], r1.w, i01);
        float i11 = PC1[0] * r1.x;
        i11 = fmaf(PC1[1], r1.y, i11);
        i11 = fmaf(PC1[2], r1.z, i11);
        i11 = fmaf(PC1[3], r1.w, i11);

        a0e = fmaf(PB0[b], i00, a0e);
        a1e = fmaf(PB1[b], i10, a1e);
        a0o = fmaf(PB0[b + 1], i01, a0o);
        a1o = fmaf(PB1[b + 1], i11, a1o);
    }
    float acc0 = PA0 * (a0e + a0o);
    float acc1 = PA1 * (a1e + a1o);

    // ---- reduce over the 16 A-segment lanes (seg = lane bits 0..3) ----
#pragma unroll
    for (int d = 1; d <= 8; d <<= 1) {
        acc0 += __shfl_xor_sync(0xffffffffu, acc0, d);
        acc1 += __shfl_xor_sync(0xffffffffu, acc1, d);
    }

    if (seg == 0) {
        dst[(batBase + lb0) * (HH * WW) + pixel] = fminf(fmaxf(acc0, 0.0f), 1.0f);
        dst[(batBase + lb1) * (HH * WW) + pixel] = fminf(fmaxf(acc1, 0.0f), 1.0f);
    }
}

extern "C" void kernel_launch(void* const* d_in, const int* in_sizes, int n_in,
                              void* d_out, int out_size) {
    // Identify inputs by size (x: 16384, tg: 2097152)
    const float* x  = (const float*)d_in[0];
    const float* tg = (const float*)d_in[1];
    if (n_in >= 2 && in_sizes[0] > in_sizes[1]) {
        x  = (const float*)d_in[1];
        tg = (const float*)d_in[0];
    }
    float* out = (float*)d_out;

    float* st;
    cudaGetSymbolAddress((void**)&st, g_state);
    float* s0 = st;
    float* s1 = st + BB * HH * WW;

    asic_layer<<<GRID, THREADS>>>(x,  tg + 0 * LHW, s0);
    asic_layer<<<GRID, THREADS>>>(s0, tg + 1 * LHW, s1);
    asic_layer<<<GRID, THREADS>>>(s1, tg + 2 * LHW, s0);
    asic_layer<<<GRID, THREADS>>>(s0, tg + 3 * LHW, out);
}

// round 10
// speedup vs baseline: 1.2267x; 1.2267x over previous
#include <cuda_runtime.h>

#define HH 32
#define WW 32
#define BB 16
#define NPOS 512
#define PIX 8              // pixels per block (contiguous in one row; 8 | 32)
#define THREADS 1024
#define GRID 128
#define SEGROW 36          // floats per A-segment (32 data + 4 pad)
#define SROW (16 * SEGROW + 4)   // 580 floats per pixel row
#define LHW (NPOS * HH * WW)
#define VROW 12            // window smem: cols per row (10 used)
#define VBAT 36            // window smem: floats per batch (3*12)

// Ping-pong state scratch (no device allocation allowed).
__device__ float g_state[2][BB * HH * WW];

__device__ __forceinline__ float sigmoidf(float x) {
    return __fdividef(1.0f, 1.0f + __expf(-x));
}

// 8 products for one bit-triple (va = MSB).
__device__ __forceinline__ void triple8(float va, float vb, float vc, float* P) {
    float ca = 1.0f - va, cb = 1.0f - vb, cc = 1.0f - vc;
    float t0 = cb * cc, t1 = cb * vc, t2 = vb * cc, t3 = vb * vc;
    P[0] = ca * t0; P[1] = ca * t1; P[2] = ca * t2; P[3] = ca * t3;
    P[4] = va * t0; P[5] = va * t1; P[6] = va * t2; P[7] = va * t3;
}

__global__ __launch_bounds__(THREADS, 1)
void asic_layer(const float* __restrict__ src,   // (B,H,W) previous state
                const float* __restrict__ tg,    // (NPOS,H,W) this layer's gates
                float* __restrict__ dst)         // (B,H,W)
{
    __shared__ __align__(16) float s_s[PIX * SROW];         // sigmoid(gates)
    __shared__ __align__(16) float s_v[BB * VBAT];          // state window halo

    const int tid = threadIdx.x;
    const int pixBase = blockIdx.x * PIX;
    const int hB = pixBase >> 5;         // block row
    const int w0 = pixBase & 31;         // block first col

    // ---- thread mapping: seg(16) x batch-pair(8) x pixel(8) ----
    const int seg  = tid & 15;           // A = top 4 bits of combo j
    const int bp   = (tid >> 4) & 7;     // batches bp and bp+8
    const int pixL = tid >> 7;           // 0..7
    const int pixel = pixBase + pixL;
    const int b0 = bp, b1 = bp + 8;

    // ================= state-INDEPENDENT prologue (runs under PDL overlap) ====
    // ---- gate LDG.128 (one combo-halfrow per thread) ----
    const int p  = tid >> 1;             // combo 0..511
    const int ih = (tid & 1) * 4;        // pixels ih..ih+3
    float4 g = *(const float4*)(tg + p * (HH * WW) + pixBase + ih);

    // ---- sigmoid + stage gates (conflict-free skewed layout) ----
    {
        int base = (p >> 5) * SEGROW + (p & 31);
        s_s[(ih + 0) * SROW + base] = sigmoidf(g.x);
        s_s[(ih + 1) * SROW + base] = sigmoidf(g.y);
        s_s[(ih + 2) * SROW + base] = sigmoidf(g.z);
        s_s[(ih + 3) * SROW + base] = sigmoidf(g.w);
    }

#if __CUDA_ARCH__ >= 900
    // Let the NEXT layer's kernel begin launching/prologue now.
    cudaTriggerProgrammaticLaunchCompletion();
    // Wait for the PREVIOUS layer's kernel to fully complete before reading state.
    cudaGridDependencySynchronize();
#endif

    // ================= state-DEPENDENT part ==================================
    // ---- halo LDG (480 distinct values: 16 batches x 3 rows x 10 cols) ----
    if (tid < BB * 30) {
        int b   = tid / 30;
        int rem = tid % 30;
        int r   = rem / 10;
        int c   = rem % 10;
        int row = (hB + r) & 31;
        int col = (w0 - 1 + c) & 31;
        s_v[b * VBAT + r * VROW + c] = __ldg(src + b * (HH * WW) + row * WW + col);
    }
    __syncthreads();

    // ---- read both batches' 3x3 windows from smem (broadcast, conflict-free) ----
    float v0[9], v1[9];
#pragma unroll
    for (int i0 = 0; i0 < 3; i0++) {
#pragma unroll
        for (int i1 = 0; i1 < 3; i1++) {
            int c = i0 * VROW + pixL + i1;
            v0[i0 * 3 + i1] = s_v[b0 * VBAT + c];
            v1[i0 * 3 + i1] = s_v[b1 * VBAT + c];
        }
    }

    // ---- partial products ----
    // bit for elem m is (j >> (8-m)) & 1:
    // A = j>>5 (m0..m3, fixed = seg), B = (j>>2)&7 (m4..m6), C = j&3 (m7,m8)
    float PB0[8], PB1[8];
    triple8(v0[4], v0[5], v0[6], PB0);
    triple8(v1[4], v1[5], v1[6], PB1);

    float PC0[4], PC1[4];
    {
        float c7 = 1.0f - v0[7], c8 = 1.0f - v0[8];
        PC0[0] = c7 * c8; PC0[1] = c7 * v0[8]; PC0[2] = v0[7] * c8; PC0[3] = v0[7] * v0[8];
        float d7 = 1.0f - v1[7], d8 = 1.0f - v1[8];
        PC1[0] = d7 * d8; PC1[1] = d7 * v1[8]; PC1[2] = v1[7] * d8; PC1[3] = v1[7] * v1[8];
    }

    const float PA0 = (((seg & 8) ? v0[0] : 1.0f - v0[0]) * ((seg & 4) ? v0[1] : 1.0f - v0[1]))
                    * (((seg & 2) ? v0[2] : 1.0f - v0[2]) * ((seg & 1) ? v0[3] : 1.0f - v0[3]));
    const float PA1 = (((seg & 8) ? v1[0] : 1.0f - v1[0]) * ((seg & 4) ? v1[1] : 1.0f - v1[1]))
                    * (((seg & 2) ? v1[2] : 1.0f - v1[2]) * ((seg & 1) ? v1[3] : 1.0f - v1[3]));

    // ---- contraction: 32 combos, fma chains, each gate read feeds 2 batches ----
    const float* sp = s_s + pixL * SROW + seg * SEGROW;
    float a0e = 0.0f, a0o = 0.0f, a1e = 0.0f, a1o = 0.0f;
#pragma unroll
    for (int b = 0; b < 8; b += 2) {
        float4 r0 = *(const float4*)(sp + b * 4);
        float4 r1 = *(const float4*)(sp + b * 4 + 4);

        float i00 = PC0[0] * r0.x;
        i00 = fmaf(PC0[1], r0.y, i00);
        i00 = fmaf(PC0[2], r0.z, i00);
        i00 = fmaf(PC0[3], r0.w, i00);
        float i10 = PC1[0] * r0.x;
        i10 = fmaf(PC1[1], r0.y, i10);
        i10 = fmaf(PC1[2], r0.z, i10);
        i10 = fmaf(PC1[3], r0.w, i10);
        float i01 = PC0[0] * r1.x;
        i01 = fmaf(PC0[1], r1.y, i01);
        i01 = fmaf(PC0[2], r1.z, i01);
        i01 = fmaf(PC0[3], r1.w, i01);
        float i11 = PC1[0] * r1.x;
        i11 = fmaf(PC1[1], r1.y, i11);
        i11 = fmaf(PC1[2], r1.z, i11);
        i11 = fmaf(PC1[3], r1.w, i11);

        a0e = fmaf(PB0[b], i00, a0e);
        a1e = fmaf(PB1[b], i10, a1e);
        a0o = fmaf(PB0[b + 1], i01, a0o);
        a1o = fmaf(PB1[b + 1], i11, a1o);
    }
    float acc0 = PA0 * (a0e + a0o);
    float acc1 = PA1 * (a1e + a1o);

    // ---- reduce over the 16 A-segment lanes (seg = lane bits 0..3) ----
#pragma unroll
    for (int d = 1; d <= 8; d <<= 1) {
        acc0 += __shfl_xor_sync(0xffffffffu, acc0, d);
        acc1 += __shfl_xor_sync(0xffffffffu, acc1, d);
    }

    if (seg == 0) {
        dst[b0 * (HH * WW) + pixel] = fminf(fmaxf(acc0, 0.0f), 1.0f);
        dst[b1 * (HH * WW) + pixel] = fminf(fmaxf(acc1, 0.0f), 1.0f);
    }
}

static inline void launch_pdl(const float* src, const float* tg, float* dst) {
    cudaLaunchConfig_t cfg = {};
    cfg.gridDim = dim3(GRID, 1, 1);
    cfg.blockDim = dim3(THREADS, 1, 1);
    cfg.dynamicSmemBytes = 0;
    cfg.stream = 0;                       // default (capture) stream
    cudaLaunchAttribute attr[1];
    attr[0].id = cudaLaunchAttributeProgrammaticStreamSerialization;
    attr[0].val.programmaticStreamSerializationAllowed = 1;
    cfg.attrs = attr;
    cfg.numAttrs = 1;
    cudaLaunchKernelEx(&cfg, asic_layer, src, tg, dst);
}

extern "C" void kernel_launch(void* const* d_in, const int* in_sizes, int n_in,
                              void* d_out, int out_size) {
    // Identify inputs by size (x: 16384, tg: 2097152)
    const float* x  = (const float*)d_in[0];
    const float* tg = (const float*)d_in[1];
    if (n_in >= 2 && in_sizes[0] > in_sizes[1]) {
        x  = (const float*)d_in[1];
        tg = (const float*)d_in[0];
    }
    float* out = (float*)d_out;

    float* st;
    cudaGetSymbolAddress((void**)&st, g_state);
    float* s0 = st;
    float* s1 = st + BB * HH * WW;

    launch_pdl(x,  tg + 0 * LHW, s0);
    launch_pdl(s0, tg + 1 * LHW, s1);
    launch_pdl(s1, tg + 2 * LHW, s0);
    launch_pdl(s0, tg + 3 * LHW, out);
}

// round 11
// speedup vs baseline: 1.2505x; 1.0194x over previous
#include <cuda_runtime.h>

#define HH 32
#define WW 32
#define BB 16
#define NPOS 512
#define PIX 8              // pixels per block (contiguous in one row)
#define THREADS 512
#define GRID 128
#define AROW 68            // floats per A-octant (64 data + 4 pad)
#define SROW 548           // floats per pixel row (8*68=544 + 4 pad)
#define LHW (NPOS * HH * WW)
#define VROW 12            // window smem: cols per row (10 used)
#define VBAT 36            // window smem: floats per batch (3*12)

// Ping-pong state scratch (no device allocation allowed).
__device__ float g_state[2][BB * HH * WW];

__device__ __forceinline__ float sigmoidf(float x) {
    return __fdividef(1.0f, 1.0f + __expf(-x));
}

// 8 products for one bit-triple (va = MSB).
__device__ __forceinline__ void triple8(float va, float vb, float vc, float* P) {
    float ca = 1.0f - va, cb = 1.0f - vb, cc = 1.0f - vc;
    float t0 = cb * cc, t1 = cb * vc, t2 = vb * cc, t3 = vb * vc;
    P[0] = ca * t0; P[1] = ca * t1; P[2] = ca * t2; P[3] = ca * t3;
    P[4] = va * t0; P[5] = va * t1; P[6] = va * t2; P[7] = va * t3;
}

__global__ __launch_bounds__(THREADS, 2)
void asic_layer(const float* __restrict__ src,   // (B,H,W) previous state
                const float* __restrict__ tg,    // (NPOS,H,W) this layer's gates
                float* __restrict__ dst)         // (B,H,W)
{
    __shared__ __align__(16) float s_s[PIX * SROW];      // sigmoid(gates)
    __shared__ __align__(16) float s_v[BB * VBAT];       // state window halo

#if __CUDA_ARCH__ >= 900
    // Allow the next layer's kernel to launch immediately; dependency safety
    // is enforced by cudaGridDependencySynchronize() below.
    cudaTriggerProgrammaticLaunchCompletion();
#endif

    const int tid = threadIdx.x;
    const int pixBase = blockIdx.x * PIX;
    const int hB = pixBase >> 5;         // block row
    const int w0 = pixBase & 31;         // block first col

    // ---- thread mapping: oct(8) x batch-pair(8) x pixel(8) ----
    const int oct  = tid & 7;            // A = top 3 bits of combo j
    const int bp   = (tid >> 3) & 7;     // batches bp and bp+8
    const int pixL = tid >> 6;           // 0..7
    const int pixel = pixBase + pixL;
    const int b0 = bp, b1 = bp + 8;

    // ================= state-INDEPENDENT prologue (overlaps prev layer) ======
    // ---- gate LDG.128 (two combo-halfrows per thread) ----
    const int p0  = tid >> 1;
    const int ih0 = (tid & 1) * 4;
    float4 g0 = *(const float4*)(tg + p0 * (HH * WW) + pixBase + ih0);
    const int c1  = tid + THREADS;
    const int p1  = c1 >> 1;
    const int ih1 = (c1 & 1) * 4;
    float4 g1 = *(const float4*)(tg + p1 * (HH * WW) + pixBase + ih1);

    // ---- sigmoid + stage gates (conflict-free skewed layout) ----
    {
        int base = (p0 >> 6) * AROW + (p0 & 63);
        s_s[(ih0 + 0) * SROW + base] = sigmoidf(g0.x);
        s_s[(ih0 + 1) * SROW + base] = sigmoidf(g0.y);
        s_s[(ih0 + 2) * SROW + base] = sigmoidf(g0.z);
        s_s[(ih0 + 3) * SROW + base] = sigmoidf(g0.w);
        base = (p1 >> 6) * AROW + (p1 & 63);
        s_s[(ih1 + 0) * SROW + base] = sigmoidf(g1.x);
        s_s[(ih1 + 1) * SROW + base] = sigmoidf(g1.y);
        s_s[(ih1 + 2) * SROW + base] = sigmoidf(g1.z);
        s_s[(ih1 + 3) * SROW + base] = sigmoidf(g1.w);
    }

#if __CUDA_ARCH__ >= 900
    // Wait for the previous layer's kernel before reading state.
    cudaGridDependencySynchronize();
#endif

    // ================= state-DEPENDENT part ==================================
    // ---- halo LDG (480 distinct values: 16 batches x 3 rows x 10 cols) ----
    if (tid < BB * 30) {
        int b   = tid / 30;
        int rem = tid % 30;
        int r   = rem / 10;
        int c   = rem % 10;
        int row = (hB + r) & 31;
        int col = (w0 - 1 + c) & 31;
        s_v[b * VBAT + r * VROW + c] = __ldg(src + b * (HH * WW) + row * WW + col);
    }
    __syncthreads();

    // ---- read both batches' 3x3 windows from smem (broadcast) ----
    float v0[9], v1[9];
#pragma unroll
    for (int i0 = 0; i0 < 3; i0++) {
#pragma unroll
        for (int i1 = 0; i1 < 3; i1++) {
            int c = i0 * VROW + pixL + i1;
            v0[i0 * 3 + i1] = s_v[b0 * VBAT + c];
            v1[i0 * 3 + i1] = s_v[b1 * VBAT + c];
        }
    }

    // ---- partial products ----
    // A = j>>6 (m0..m2, fixed = oct), B = (j>>3)&7 (m3..m5), C = j&7 (m6..m8)
    float PB0[8], PB1[8], PC0[8], PC1[8];
    triple8(v0[3], v0[4], v0[5], PB0);
    triple8(v0[6], v0[7], v0[8], PC0);
    triple8(v1[3], v1[4], v1[5], PB1);
    triple8(v1[6], v1[7], v1[8], PC1);
    const float PA0 = ((oct & 4) ? v0[0] : 1.0f - v0[0])
                    * ((oct & 2) ? v0[1] : 1.0f - v0[1])
                    * ((oct & 1) ? v0[2] : 1.0f - v0[2]);
    const float PA1 = ((oct & 4) ? v1[0] : 1.0f - v1[0])
                    * ((oct & 2) ? v1[1] : 1.0f - v1[1])
                    * ((oct & 1) ? v1[2] : 1.0f - v1[2]);

    // ---- contraction: 64 combos, each gate read feeds 2 batches ----
    const float* sp = s_s + pixL * SROW + oct * AROW;
    float a0e = 0.0f, a0o = 0.0f, a1e = 0.0f, a1o = 0.0f;
#pragma unroll
    for (int b = 0; b < 8; b += 2) {
        float4 r0 = *(const float4*)(sp + b * 8);
        float4 r1 = *(const float4*)(sp + b * 8 + 4);
        float4 r2 = *(const float4*)(sp + b * 8 + 8);
        float4 r3 = *(const float4*)(sp + b * 8 + 12);

        float i00 = PC0[0] * r0.x;
        i00 = fmaf(PC0[1], r0.y, i00);
        i00 = fmaf(PC0[2], r0.z, i00);
        i00 = fmaf(PC0[3], r0.w, i00);
        i00 = fmaf(PC0[4], r1.x, i00);
        i00 = fmaf(PC0[5], r1.y, i00);
        i00 = fmaf(PC0[6], r1.z, i00);
        i00 = fmaf(PC0[7], r1.w, i00);
        float i10 = PC1[0] * r0.x;
        i10 = fmaf(PC1[1], r0.y, i10);
        i10 = fmaf(PC1[2], r0.z, i10);
        i10 = fmaf(PC1[3], r0.w, i10);
        i10 = fmaf(PC1[4], r1.x, i10);
        i10 = fmaf(PC1[5], r1.y, i10);
        i10 = fmaf(PC1[6], r1.z, i10);
        i10 = fmaf(PC1[7], r1.w, i10);
        float i01 = PC0[0] * r2.x;
        i01 = fmaf(PC0[1], r2.y, i01);
        i01 = fmaf(PC0[2], r2.z, i01);
        i01 = fmaf(PC0[3], r2.w, i01);
        i01 = fmaf(PC0[4], r3.x, i01);
        i01 = fmaf(PC0[5], r3.y, i01);
        i01 = fmaf(PC0[6], r3.z, i01);
        i01 = fmaf(PC0[7], r3.w, i01);
        float i11 = PC1[0] * r2.x;
        i11 = fmaf(PC1[1], r2.y, i11);
        i11 = fmaf(PC1[2], r2.z, i11);
        i11 = fmaf(PC1[3], r2.w, i11);
        i11 = fmaf(PC1[4], r3.x, i11);
        i11 = fmaf(PC1[5], r3.y, i11);
        i11 = fmaf(PC1[6], r3.z, i11);
        i11 = fmaf(PC1[7], r3.w, i11);

        a0e = fmaf(PB0[b], i00, a0e);
        a1e = fmaf(PB1[b], i10, a1e);
        a0o = fmaf(PB0[b + 1], i01, a0o);
        a1o = fmaf(PB1[b + 1], i11, a1o);
    }
    float acc0 = PA0 * (a0e + a0o);
    float acc1 = PA1 * (a1e + a1o);

    // ---- reduce over the 8 A-octant lanes (oct = lane bits 0..2) ----
#pragma unroll
    for (int d = 1; d <= 4; d <<= 1) {
        acc0 += __shfl_xor_sync(0xffffffffu, acc0, d);
        acc1 += __shfl_xor_sync(0xffffffffu, acc1, d);
    }

    if (oct == 0) {
        dst[b0 * (HH * WW) + pixel] = fminf(fmaxf(acc0, 0.0f), 1.0f);
        dst[b1 * (HH * WW) + pixel] = fminf(fmaxf(acc1, 0.0f), 1.0f);
    }
}

static inline void launch_pdl(const float* src, const float* tg, float* dst) {
    cudaLaunchConfig_t cfg = {};
    cfg.gridDim = dim3(GRID, 1, 1);
    cfg.blockDim = dim3(THREADS, 1, 1);
    cfg.dynamicSmemBytes = 0;
    cfg.stream = 0;                       // default (capture) stream
    cudaLaunchAttribute attr[1];
    attr[0].id = cudaLaunchAttributeProgrammaticStreamSerialization;
    attr[0].val.programmaticStreamSerializationAllowed = 1;
    cfg.attrs = attr;
    cfg.numAttrs = 1;
    cudaLaunchKernelEx(&cfg, asic_layer, src, tg, dst);
}

extern "C" void kernel_launch(void* const* d_in, const int* in_sizes, int n_in,
                              void* d_out, int out_size) {
    // Identify inputs by size (x: 16384, tg: 2097152)
    const float* x  = (const float*)d_in[0];
    const float* tg = (const float*)d_in[1];
    if (n_in >= 2 && in_sizes[0] > in_sizes[1]) {
        x  = (const float*)d_in[1];
        tg = (const float*)d_in[0];
    }
    float* out = (float*)d_out;

    float* st;
    cudaGetSymbolAddress((void**)&st, g_state);
    float* s0 = st;
    float* s1 = st + BB * HH * WW;

    launch_pdl(x,  tg + 0 * LHW, s0);
    launch_pdl(s0, tg + 1 * LHW, s1);
    launch_pdl(s1, tg + 2 * LHW, s0);
    launch_pdl(s0, tg + 3 * LHW, out);
}